// round 12
// baseline (speedup 1.0000x reference)
#include <cuda_runtime.h>

// CharAttention: B=512, W=128, c=24, C=32, H=2, D=16.
// Only the row at x_end_idx is needed -> one causal attention row per (b,w)
// tile with folded weights:
//   M_h = W_q_h @ W_k_h^T / sqrt(D)   (score_h(k) = x_q M_h x_k^T)
//   P_h = W_v_h @ W_proj[h*D:(h+1)*D] (y = sum_h (sum_k att_hk x_k) P_h)
// out = x[idx] + y.
// R3/R6: warp-pair per tile + pipeline + no-max softmax.        [67.5 us]
// R7/R9 micro-opts NEUTRAL, R8 key-split REGR, R10 one-warp-per-tile REGR
//   (latency-bound: throughput ~ resident warps; instr/wf tweaks don't move).
// R11: occupancy push on the R6 skeleton — 64-thread blocks (one pair),
//   plain __syncthreads, direct LDG->STS prefetch (no live staging regs),
//   __launch_bounds__(64,10) caps regs at 102 -> 20 warps/SM (vs 16).

#define NTILES (512 * 128)
#define CBLK 24
#define EMB 32
#define XSTRIDE 36      // pad (mult of 4, %32==4): conflict-free float4-row AND scalar-column
#define THREADS 64      // one warp-pair per block
#define GRID 1480       // 10 blocks/SM * 148 SMs -> fully persistent
#define PAIRSTRIDE GRID

__device__ float g_M[2 * 32 * 32];  // [h][i][j]
__device__ float g_P[2 * 32 * 32];  // [h][i][j]

__global__ void precompute_kernel(const float* __restrict__ w_attn,
                                  const float* __restrict__ w_proj) {
    int t = blockIdx.x * blockDim.x + threadIdx.x;
    if (t >= 4096) return;
    int which = t >> 11;   // 0 = M, 1 = P
    int r = t & 2047;
    int h = r >> 10;
    int i = (r >> 5) & 31;
    int j = r & 31;
    float acc = 0.f;
    if (which == 0) {
        #pragma unroll
        for (int d = 0; d < 16; d++)
            acc += w_attn[i * 96 + h * 16 + d] * w_attn[j * 96 + 32 + h * 16 + d];
        g_M[r] = acc * 0.25f;  // 1/sqrt(16)
    } else {
        #pragma unroll
        for (int d = 0; d < 16; d++)
            acc += w_attn[i * 96 + 64 + h * 16 + d] * w_proj[(h * 16 + d) * 32 + j];
        g_P[r] = acc;
    }
}

__global__ void __launch_bounds__(THREADS, 10)
attn_kernel(const float* __restrict__ x, const int* __restrict__ endidx,
            float* __restrict__ out) {
    __shared__ __align__(16) float xs[2][CBLK][XSTRIDE];
    __shared__ float4 qs4[2][8];     // per-warp private q copy
    __shared__ float4 us4[2][8];     // per-warp u_h
    __shared__ float4 ss4[2][8];     // per-warp s_h
    __shared__ float  atts[2][32];
    __shared__ float  y1s[2][32];    // head-1 output, parity-buffered

    const int lane = threadIdx.x & 31;
    const int h    = threadIdx.x >> 5;   // head handled by this warp
    const int pt   = threadIdx.x;        // thread within pair (0..63)

    // This warp's head's folded-weight columns (lane = output dim j).
    float Mc[32], Pc[32];
    {
        const float* Mb = g_M + h * 1024 + lane;
        const float* Pb = g_P + h * 1024 + lane;
        #pragma unroll
        for (int i = 0; i < 32; i++) { Mc[i] = Mb[i * 32]; Pc[i] = Pb[i * 32]; }
    }

    int bw = blockIdx.x;

    // ---- Pipeline prologue: idx two tiles ahead; stage tile n into buf 0.
    int id  = __ldg(endidx + bw);                                 // tile n
    int bw1 = bw + PAIRSTRIDE;
    int id1 = (bw1 < NTILES) ? __ldg(endidx + bw1) : 0;           // tile n+1

    {
        const float* xt = x + (size_t)bw * (CBLK * EMB);
        const int totalF = (id + 1) * EMB;
        #pragma unroll
        for (int k = 0; k < 3; k++) {
            int e = pt * 4 + k * 256;
            if (e < totalF)
                *reinterpret_cast<float4*>(&xs[0][e >> 5][e & 31]) =
                    *reinterpret_cast<const float4*>(xt + e);
        }
    }

    int buf = 0;
    int   prev_bw = -1;
    float prev_qv = 0.f, prev_y = 0.f;

    while (bw < NTILES) {
        const int nk = id + 1;
        __syncthreads();   // drains prior STS into xs[buf]; pair-wide sync

        // ---- Store tile n-1 output (warp0); y1s written by warp1 pre-bar.
        if (h == 0 && prev_bw >= 0)
            out[prev_bw * EMB + lane] = prev_qv + prev_y + y1s[buf ^ 1][lane];

        // ---- Prefetch: idx n+2; tile n+1 direct LDG->STS into idle buffer
        //      (transient regs only; STS drains at next __syncthreads).
        const int bw2 = bw1 + PAIRSTRIDE;
        const int id2 = (bw2 < NTILES) ? __ldg(endidx + bw2) : 0;
        if (bw1 < NTILES) {
            const float* xt = x + (size_t)bw1 * (CBLK * EMB);
            const int totalF = (id1 + 1) * EMB;
            #pragma unroll
            for (int k = 0; k < 3; k++) {
                int e = pt * 4 + k * 256;
                if (e < totalF)
                    *reinterpret_cast<float4*>(&xs[buf ^ 1][e >> 5][e & 31]) =
                        *reinterpret_cast<const float4*>(xt + e);
            }
        }

        // ---- q = x[idx] (conflict-free column read); private warp copy.
        const float qv = xs[buf][id][lane];
        reinterpret_cast<float*>(qs4[h])[lane] = qv;
        __syncwarp();

        // ---- u = q @ M_h   (lane = output dim j)
        float u = 0.f;
        #pragma unroll
        for (int i4 = 0; i4 < 8; i4++) {
            const float4 q = qs4[h][i4];
            const int i = i4 * 4;
            u = fmaf(q.x, Mc[i + 0], u);
            u = fmaf(q.y, Mc[i + 1], u);
            u = fmaf(q.z, Mc[i + 2], u);
            u = fmaf(q.w, Mc[i + 3], u);
        }
        reinterpret_cast<float*>(us4[h])[lane] = u;
        __syncwarp();

        // ---- scores: lane = key r; sc = u . x_r (float4 row reads)
        float e = 0.f;
        if (lane < nk) {
            const float4* xr = reinterpret_cast<const float4*>(&xs[buf][lane][0]);
            float a = 0.f;
            #pragma unroll
            for (int i4 = 0; i4 < 8; i4++) {
                const float4 uu = us4[h][i4];   // broadcast
                const float4 xv = xr[i4];
                a = fmaf(uu.x, xv.x, a);
                a = fmaf(uu.y, xv.y, a);
                a = fmaf(uu.z, xv.z, a);
                a = fmaf(uu.w, xv.w, a);
            }
            // No max-shift: std(sc)=4, overflow needs sc>88 (22 sigma) — safe.
            e = __expf(a);
        }
        atts[h][lane] = e;
        __syncwarp();

        // ---- sum reduce; issues alongside the s-loop (consumed at divide).
        float sum = e;
        #pragma unroll
        for (int o = 16; o > 0; o >>= 1)
            sum += __shfl_xor_sync(0xffffffffu, sum, o);

        // ---- s = sum_r att_r * x_r   (lane = dim i)
        float a0 = 0.f;
        for (int r = 0; r < nk; r++)
            a0 = fmaf(atts[h][r], xs[buf][r][lane], a0);
        a0 = __fdividef(a0, sum);
        reinterpret_cast<float*>(ss4[h])[lane] = a0;
        __syncwarp();

        // ---- y_h = s @ P_h   (lane = output dim j)
        float y = 0.f;
        #pragma unroll
        for (int i4 = 0; i4 < 8; i4++) {
            const float4 sv = ss4[h][i4];
            const int i = i4 * 4;
            y = fmaf(sv.x, Pc[i + 0], y);
            y = fmaf(sv.y, Pc[i + 1], y);
            y = fmaf(sv.z, Pc[i + 2], y);
            y = fmaf(sv.w, Pc[i + 3], y);
        }

        // ---- defer combine: warp1 publishes, warp0 stores after next bar.
        if (h == 1) {
            y1s[buf][lane] = y;
        } else {
            prev_qv = qv; prev_y = y; prev_bw = bw;
        }

        bw = bw1; id = id1;
        bw1 = bw2; id1 = id2;
        buf ^= 1;
    }

    // ---- Epilogue: flush last tile's output.
    __syncthreads();
    if (h == 0 && prev_bw >= 0)
        out[prev_bw * EMB + lane] = prev_qv + prev_y + y1s[buf ^ 1][lane];
}

extern "C" void kernel_launch(void* const* d_in, const int* in_sizes, int n_in,
                              void* d_out, int out_size) {
    const float* x      = (const float*)d_in[0];
    const int*   endidx = (const int*)d_in[1];
    const float* w_attn = (const float*)d_in[2];
    const float* w_proj = (const float*)d_in[3];
    float* out = (float*)d_out;

    precompute_kernel<<<16, 256>>>(w_attn, w_proj);
    attn_kernel<<<GRID, THREADS>>>(x, endidx, out);
}

// round 13
// speedup vs baseline: 1.4028x; 1.4028x over previous
#include <cuda_runtime.h>

// CharAttention: B=512, W=128, c=24, C=32, H=2, D=16.
// Only the row at x_end_idx is needed -> one causal attention row per (b,w)
// tile with folded weights:
//   M_h = W_q_h @ W_k_h^T / sqrt(D)   (score_h(k) = x_q M_h x_k^T)
//   P_h = W_v_h @ W_proj[h*D:(h+1)*D] (y = sum_h (sum_k att_hk x_k) P_h)
// out = x[idx] + y.
// R3/R6: warp-pair per tile + pipeline + no-max softmax.        [67.5 us]
// R11: reg diet to 96 regs worked, but 64-thread blocks put all warps on
//   SMSP 0/1 (wid%4 mapping) -> half the SM idle -> 2x REGRESSION.
// R12: same reg diet on the R6 skeleton with an SMSP-correct shape:
//   320-thread blocks (5 pairs), launch_bounds(320,2) -> reg cap 102,
//   2 blocks/SM = 20 warps/SM spread 3/3/2/2; named pair barriers;
//   direct LDG->STS prefetch (no live staging registers).

#define NTILES (512 * 128)
#define CBLK 24
#define EMB 32
#define XSTRIDE 36      // pad (mult of 4, %32==4): conflict-free float4-row AND scalar-column
#define PAIRS_PER_BLK 5
#define THREADS (PAIRS_PER_BLK * 64)   // 320
#define GRID 296        // 2 blocks/SM * 148 SMs -> fully persistent
#define PAIRSTRIDE (GRID * PAIRS_PER_BLK)

__device__ float g_M[2 * 32 * 32];  // [h][i][j]
__device__ float g_P[2 * 32 * 32];  // [h][i][j]

__global__ void precompute_kernel(const float* __restrict__ w_attn,
                                  const float* __restrict__ w_proj) {
    int t = blockIdx.x * blockDim.x + threadIdx.x;
    if (t >= 4096) return;
    int which = t >> 11;   // 0 = M, 1 = P
    int r = t & 2047;
    int h = r >> 10;
    int i = (r >> 5) & 31;
    int j = r & 31;
    float acc = 0.f;
    if (which == 0) {
        #pragma unroll
        for (int d = 0; d < 16; d++)
            acc += w_attn[i * 96 + h * 16 + d] * w_attn[j * 96 + 32 + h * 16 + d];
        g_M[r] = acc * 0.25f;  // 1/sqrt(16)
    } else {
        #pragma unroll
        for (int d = 0; d < 16; d++)
            acc += w_attn[i * 96 + 64 + h * 16 + d] * w_proj[(h * 16 + d) * 32 + j];
        g_P[r] = acc;
    }
}

__global__ void __launch_bounds__(THREADS, 2)
attn_kernel(const float* __restrict__ x, const int* __restrict__ endidx,
            float* __restrict__ out) {
    __shared__ __align__(16) float xs[2][PAIRS_PER_BLK][CBLK][XSTRIDE];
    __shared__ float4 qs4[2 * PAIRS_PER_BLK][8];   // per-warp private q copy
    __shared__ float4 us4[2 * PAIRS_PER_BLK][8];   // per-warp u_h
    __shared__ float4 ss4[2 * PAIRS_PER_BLK][8];   // per-warp s_h
    __shared__ float  atts[2 * PAIRS_PER_BLK][32];
    __shared__ float  y1s[PAIRS_PER_BLK][2][32];   // head-1 output, parity-buffered

    const int w    = threadIdx.x >> 5;
    const int lane = threadIdx.x & 31;
    const int p    = w >> 1;             // pair in block (0..4)
    const int h    = w & 1;              // head handled by this warp
    const int pt   = (h << 5) | lane;    // thread within pair (0..63)
    const int barId = p + 1;

    // This warp's head's folded-weight columns (lane = output dim j).
    float Mc[32], Pc[32];
    {
        const float* Mb = g_M + h * 1024 + lane;
        const float* Pb = g_P + h * 1024 + lane;
        #pragma unroll
        for (int i = 0; i < 32; i++) { Mc[i] = Mb[i * 32]; Pc[i] = Pb[i * 32]; }
    }

    int bw = blockIdx.x * PAIRS_PER_BLK + p;

    // ---- Pipeline prologue: idx two tiles ahead; stage tile n into buf 0.
    int id  = __ldg(endidx + bw);                                 // tile n
    int bw1 = bw + PAIRSTRIDE;
    int id1 = (bw1 < NTILES) ? __ldg(endidx + bw1) : 0;           // tile n+1

    {
        const float* xt = x + (size_t)bw * (CBLK * EMB);
        const int totalF = (id + 1) * EMB;
        #pragma unroll
        for (int k = 0; k < 3; k++) {
            int e = pt * 4 + k * 256;
            if (e < totalF)
                *reinterpret_cast<float4*>(&xs[0][p][e >> 5][e & 31]) =
                    *reinterpret_cast<const float4*>(xt + e);
        }
    }

    int buf = 0;
    int   prev_bw = -1;
    float prev_qv = 0.f, prev_y = 0.f;

    while (bw < NTILES) {
        const int nk = id + 1;
        asm volatile("bar.sync %0, 64;" :: "r"(barId) : "memory");  // STS drained

        // ---- Store tile n-1 output (warp0); y1s written by warp1 pre-bar.
        if (h == 0 && prev_bw >= 0)
            out[prev_bw * EMB + lane] = prev_qv + prev_y + y1s[p][buf ^ 1][lane];

        // ---- Prefetch: idx n+2; tile n+1 direct LDG->STS into idle buffer
        //      (transient regs only; STS drains at next pair barrier).
        const int bw2 = bw1 + PAIRSTRIDE;
        const int id2 = (bw2 < NTILES) ? __ldg(endidx + bw2) : 0;
        if (bw1 < NTILES) {
            const float* xt = x + (size_t)bw1 * (CBLK * EMB);
            const int totalF = (id1 + 1) * EMB;
            #pragma unroll
            for (int k = 0; k < 3; k++) {
                int e = pt * 4 + k * 256;
                if (e < totalF)
                    *reinterpret_cast<float4*>(&xs[buf ^ 1][p][e >> 5][e & 31]) =
                        *reinterpret_cast<const float4*>(xt + e);
            }
        }

        // ---- q = x[idx] (conflict-free column read); private warp copy.
        const float qv = xs[buf][p][id][lane];
        reinterpret_cast<float*>(qs4[w])[lane] = qv;
        __syncwarp();

        // ---- u = q @ M_h   (lane = output dim j)
        float u = 0.f;
        #pragma unroll
        for (int i4 = 0; i4 < 8; i4++) {
            const float4 q = qs4[w][i4];
            const int i = i4 * 4;
            u = fmaf(q.x, Mc[i + 0], u);
            u = fmaf(q.y, Mc[i + 1], u);
            u = fmaf(q.z, Mc[i + 2], u);
            u = fmaf(q.w, Mc[i + 3], u);
        }
        reinterpret_cast<float*>(us4[w])[lane] = u;
        __syncwarp();

        // ---- scores: lane = key r; sc = u . x_r (float4 row reads)
        float e = 0.f;
        if (lane < nk) {
            const float4* xr = reinterpret_cast<const float4*>(&xs[buf][p][lane][0]);
            float a = 0.f;
            #pragma unroll
            for (int i4 = 0; i4 < 8; i4++) {
                const float4 uu = us4[w][i4];   // broadcast
                const float4 xv = xr[i4];
                a = fmaf(uu.x, xv.x, a);
                a = fmaf(uu.y, xv.y, a);
                a = fmaf(uu.z, xv.z, a);
                a = fmaf(uu.w, xv.w, a);
            }
            // No max-shift: std(sc)=4, overflow needs sc>88 (22 sigma) — safe.
            e = __expf(a);
        }
        atts[w][lane] = e;
        __syncwarp();

        // ---- sum reduce; issues alongside the s-loop (consumed at divide).
        float sum = e;
        #pragma unroll
        for (int o = 16; o > 0; o >>= 1)
            sum += __shfl_xor_sync(0xffffffffu, sum, o);

        // ---- s = sum_r att_r * x_r   (lane = dim i)
        float a0 = 0.f;
        for (int r = 0; r < nk; r++)
            a0 = fmaf(atts[w][r], xs[buf][p][r][lane], a0);
        a0 = __fdividef(a0, sum);
        reinterpret_cast<float*>(ss4[w])[lane] = a0;
        __syncwarp();

        // ---- y_h = s @ P_h   (lane = output dim j)
        float y = 0.f;
        #pragma unroll
        for (int i4 = 0; i4 < 8; i4++) {
            const float4 sv = ss4[w][i4];
            const int i = i4 * 4;
            y = fmaf(sv.x, Pc[i + 0], y);
            y = fmaf(sv.y, Pc[i + 1], y);
            y = fmaf(sv.z, Pc[i + 2], y);
            y = fmaf(sv.w, Pc[i + 3], y);
        }

        // ---- defer combine: warp1 publishes, warp0 stores after next bar.
        if (h == 1) {
            y1s[p][buf][lane] = y;
        } else {
            prev_qv = qv; prev_y = y; prev_bw = bw;
        }

        bw = bw1; id = id1;
        bw1 = bw2; id1 = id2;
        buf ^= 1;
    }

    // ---- Epilogue: flush last tile's output.
    asm volatile("bar.sync %0, 64;" :: "r"(barId) : "memory");
    if (h == 0 && prev_bw >= 0)
        out[prev_bw * EMB + lane] = prev_qv + prev_y + y1s[p][buf ^ 1][lane];
}

extern "C" void kernel_launch(void* const* d_in, const int* in_sizes, int n_in,
                              void* d_out, int out_size) {
    const float* x      = (const float*)d_in[0];
    const int*   endidx = (const int*)d_in[1];
    const float* w_attn = (const float*)d_in[2];
    const float* w_proj = (const float*)d_in[3];
    float* out = (float*)d_out;

    precompute_kernel<<<16, 256>>>(w_attn, w_proj);
    attn_kernel<<<GRID, THREADS>>>(x, endidx, out);
}

// round 14
// speedup vs baseline: 1.7143x; 1.2220x over previous
#include <cuda_runtime.h>

// CharAttention: B=512, W=128, c=24, C=32, H=2, D=16.
// Only the row at x_end_idx is needed -> one causal attention row per (b,w)
// tile with folded weights:
//   M_h = W_q_h @ W_k_h^T / sqrt(D)   (score_h(k) = x_q M_h x_k^T)
//   P_h = W_v_h @ W_proj[h*D:(h+1)*D] (y = sum_h (sum_k att_hk x_k) P_h)
// out = x[idx] + y.
// R3/R6: warp-pair per tile + pipeline + no-max softmax.        [67.5 us]
// R10/R11/R12: every LDG->STS prefetch variant REGRESSED — the STS blocks
//   on the LDG scoreboard INSIDE the tile (issue 45%), killing the pipeline;
//   register staging avoided that but costs 128 regs (16 warps cap).
// R13: cp.async (LDGSTS) prefetch — register-free AND non-blocking:
//   issue cp.async for tile n+1 during tile n, cp.async.wait_group 0 at the
//   top of iteration n+1 (a full tile of slack), then the pair barrier.
//   Keeps R12's 320-thread / ~96-reg / 20-warp shape.

#define NTILES (512 * 128)
#define CBLK 24
#define EMB 32
#define XSTRIDE 36      // pad (mult of 4, %32==4): conflict-free float4-row AND scalar-column
#define PAIRS_PER_BLK 5
#define THREADS (PAIRS_PER_BLK * 64)   // 320
#define GRID 296        // 2 blocks/SM * 148 SMs -> fully persistent
#define PAIRSTRIDE (GRID * PAIRS_PER_BLK)

__device__ float g_M[2 * 32 * 32];  // [h][i][j]
__device__ float g_P[2 * 32 * 32];  // [h][i][j]

__global__ void precompute_kernel(const float* __restrict__ w_attn,
                                  const float* __restrict__ w_proj) {
    int t = blockIdx.x * blockDim.x + threadIdx.x;
    if (t >= 4096) return;
    int which = t >> 11;   // 0 = M, 1 = P
    int r = t & 2047;
    int h = r >> 10;
    int i = (r >> 5) & 31;
    int j = r & 31;
    float acc = 0.f;
    if (which == 0) {
        #pragma unroll
        for (int d = 0; d < 16; d++)
            acc += w_attn[i * 96 + h * 16 + d] * w_attn[j * 96 + 32 + h * 16 + d];
        g_M[r] = acc * 0.25f;  // 1/sqrt(16)
    } else {
        #pragma unroll
        for (int d = 0; d < 16; d++)
            acc += w_attn[i * 96 + 64 + h * 16 + d] * w_proj[(h * 16 + d) * 32 + j];
        g_P[r] = acc;
    }
}

__device__ __forceinline__ unsigned smem_u32(const void* p) {
    return (unsigned)__cvta_generic_to_shared(p);
}

__global__ void __launch_bounds__(THREADS, 2)
attn_kernel(const float* __restrict__ x, const int* __restrict__ endidx,
            float* __restrict__ out) {
    __shared__ __align__(16) float xs[2][PAIRS_PER_BLK][CBLK][XSTRIDE];
    __shared__ float4 qs4[2 * PAIRS_PER_BLK][8];   // per-warp private q copy
    __shared__ float4 us4[2 * PAIRS_PER_BLK][8];   // per-warp u_h
    __shared__ float4 ss4[2 * PAIRS_PER_BLK][8];   // per-warp s_h
    __shared__ float  atts[2 * PAIRS_PER_BLK][32];
    __shared__ float  y1s[PAIRS_PER_BLK][2][32];   // head-1 output, parity-buffered

    const int w    = threadIdx.x >> 5;
    const int lane = threadIdx.x & 31;
    const int p    = w >> 1;             // pair in block (0..4)
    const int h    = w & 1;              // head handled by this warp
    const int pt   = (h << 5) | lane;    // thread within pair (0..63)
    const int barId = p + 1;

    // This warp's head's folded-weight columns (lane = output dim j).
    float Mc[32], Pc[32];
    {
        const float* Mb = g_M + h * 1024 + lane;
        const float* Pb = g_P + h * 1024 + lane;
        #pragma unroll
        for (int i = 0; i < 32; i++) { Mc[i] = Mb[i * 32]; Pc[i] = Pb[i * 32]; }
    }

    int bw = blockIdx.x * PAIRS_PER_BLK + p;

    // ---- Pipeline prologue: idx two tiles ahead; async-stage tile n.
    int id  = __ldg(endidx + bw);                                 // tile n
    int bw1 = bw + PAIRSTRIDE;
    int id1 = (bw1 < NTILES) ? __ldg(endidx + bw1) : 0;           // tile n+1

    {
        const float* xt = x + (size_t)bw * (CBLK * EMB);
        const int totalF = (id + 1) * EMB;
        #pragma unroll
        for (int k = 0; k < 3; k++) {
            int e = pt * 4 + k * 256;
            if (e < totalF) {
                unsigned dst = smem_u32(&xs[0][p][e >> 5][e & 31]);
                asm volatile("cp.async.cg.shared.global [%0], [%1], 16;"
                             :: "r"(dst), "l"(xt + e) : "memory");
            }
        }
        asm volatile("cp.async.commit_group;" ::: "memory");
    }

    int buf = 0;
    int   prev_bw = -1;
    float prev_qv = 0.f, prev_y = 0.f;

    while (bw < NTILES) {
        const int nk = id + 1;

        // ---- Wait for my async copies into xs[buf], then pair barrier.
        asm volatile("cp.async.wait_group 0;" ::: "memory");
        asm volatile("bar.sync %0, 64;" :: "r"(barId) : "memory");

        // ---- Store tile n-1 output (warp0); y1s written by warp1 pre-bar.
        if (h == 0 && prev_bw >= 0)
            out[prev_bw * EMB + lane] = prev_qv + prev_y + y1s[p][buf ^ 1][lane];

        // ---- Prefetch: idx n+2; tile n+1 via cp.async into the idle buffer
        //      (register-free, non-blocking; waited at next iteration's top).
        const int bw2 = bw1 + PAIRSTRIDE;
        const int id2 = (bw2 < NTILES) ? __ldg(endidx + bw2) : 0;
        if (bw1 < NTILES) {
            const float* xt = x + (size_t)bw1 * (CBLK * EMB);
            const int totalF = (id1 + 1) * EMB;
            #pragma unroll
            for (int k = 0; k < 3; k++) {
                int e = pt * 4 + k * 256;
                if (e < totalF) {
                    unsigned dst = smem_u32(&xs[buf ^ 1][p][e >> 5][e & 31]);
                    asm volatile("cp.async.cg.shared.global [%0], [%1], 16;"
                                 :: "r"(dst), "l"(xt + e) : "memory");
                }
            }
        }
        asm volatile("cp.async.commit_group;" ::: "memory");

        // ---- q = x[idx] (conflict-free column read); private warp copy.
        const float qv = xs[buf][p][id][lane];
        reinterpret_cast<float*>(qs4[w])[lane] = qv;
        __syncwarp();

        // ---- u = q @ M_h   (lane = output dim j)
        float u = 0.f;
        #pragma unroll
        for (int i4 = 0; i4 < 8; i4++) {
            const float4 q = qs4[w][i4];
            const int i = i4 * 4;
            u = fmaf(q.x, Mc[i + 0], u);
            u = fmaf(q.y, Mc[i + 1], u);
            u = fmaf(q.z, Mc[i + 2], u);
            u = fmaf(q.w, Mc[i + 3], u);
        }
        reinterpret_cast<float*>(us4[w])[lane] = u;
        __syncwarp();

        // ---- scores: lane = key r; sc = u . x_r (float4 row reads)
        float e = 0.f;
        if (lane < nk) {
            const float4* xr = reinterpret_cast<const float4*>(&xs[buf][p][lane][0]);
            float a = 0.f;
            #pragma unroll
            for (int i4 = 0; i4 < 8; i4++) {
                const float4 uu = us4[w][i4];   // broadcast
                const float4 xv = xr[i4];
                a = fmaf(uu.x, xv.x, a);
                a = fmaf(uu.y, xv.y, a);
                a = fmaf(uu.z, xv.z, a);
                a = fmaf(uu.w, xv.w, a);
            }
            // No max-shift: std(sc)=4, overflow needs sc>88 (22 sigma) — safe.
            e = __expf(a);
        }
        atts[w][lane] = e;
        __syncwarp();

        // ---- sum reduce; issues alongside the s-loop (consumed at divide).
        float sum = e;
        #pragma unroll
        for (int o = 16; o > 0; o >>= 1)
            sum += __shfl_xor_sync(0xffffffffu, sum, o);

        // ---- s = sum_r att_r * x_r   (lane = dim i)
        float a0 = 0.f;
        for (int r = 0; r < nk; r++)
            a0 = fmaf(atts[w][r], xs[buf][p][r][lane], a0);
        a0 = __fdividef(a0, sum);
        reinterpret_cast<float*>(ss4[w])[lane] = a0;
        __syncwarp();

        // ---- y_h = s @ P_h   (lane = output dim j)
        float y = 0.f;
        #pragma unroll
        for (int i4 = 0; i4 < 8; i4++) {
            const float4 sv = ss4[w][i4];
            const int i = i4 * 4;
            y = fmaf(sv.x, Pc[i + 0], y);
            y = fmaf(sv.y, Pc[i + 1], y);
            y = fmaf(sv.z, Pc[i + 2], y);
            y = fmaf(sv.w, Pc[i + 3], y);
        }

        // ---- defer combine: warp1 publishes, warp0 stores after next bar.
        if (h == 1) {
            y1s[p][buf][lane] = y;
        } else {
            prev_qv = qv; prev_y = y; prev_bw = bw;
        }

        bw = bw1; id = id1;
        bw1 = bw2; id1 = id2;
        buf ^= 1;
    }

    // ---- Epilogue: flush last tile's output.
    asm volatile("bar.sync %0, 64;" :: "r"(barId) : "memory");
    if (h == 0 && prev_bw >= 0)
        out[prev_bw * EMB + lane] = prev_qv + prev_y + y1s[p][buf ^ 1][lane];
}

extern "C" void kernel_launch(void* const* d_in, const int* in_sizes, int n_in,
                              void* d_out, int out_size) {
    const float* x      = (const float*)d_in[0];
    const int*   endidx = (const int*)d_in[1];
    const float* w_attn = (const float*)d_in[2];
    const float* w_proj = (const float*)d_in[3];
    float* out = (float*)d_out;

    precompute_kernel<<<16, 256>>>(w_attn, w_proj);
    attn_kernel<<<GRID, THREADS>>>(x, endidx, out);
}

// round 17
// speedup vs baseline: 1.8731x; 1.0926x over previous
#include <cuda_runtime.h>

// CharAttention: B=512, W=128, c=24, C=32, H=2, D=16.
// Only the row at x_end_idx is needed -> one causal attention row per (b,w)
// tile with folded weights:
//   M_h = W_q_h @ W_k_h^T / sqrt(D)   (score_h(k) = x_q M_h x_k^T)
//   P_h = W_v_h @ W_proj[h*D:(h+1)*D] (y = sum_h (sum_k att_hk x_k) P_h)
// out = x[idx] + y.
// R6: warp-pair/tile + reg-staged pipeline + no-max softmax.    [67.5 us]
// R13: cp.async prefetch, 20 warps/SM                           [69.3 us]
// Plateau: all shapes land 67-70 -> per-warp stall exposure binds.
// R14: TWO tiles interleaved per warp-pair per iteration (A=bw, B=bw+stride):
//   every smem/FMA chain has an independent twin to dual-issue against;
//   bar + syncwarps amortize over 2 tiles. cp.async keeps prefetch
//   register-free so 64 weight regs + doubled tile state fit in 128.

#define NTILES (512 * 128)
#define CBLK 24
#define EMB 32
#define XSTRIDE 36      // pad (mult of 4, %32==4): conflict-free float4-row AND scalar-column
#define PAIRS_PER_BLK 4
#define THREADS (PAIRS_PER_BLK * 64)   // 256
#define GRID 296        // 2 blocks/SM * 148 SMs -> fully persistent
#define PAIRSTRIDE (GRID * PAIRS_PER_BLK)   // 1184
#define STEP (2 * PAIRSTRIDE)               // 2 tiles per iteration

__device__ float g_M[2 * 32 * 32];  // [h][i][j]
__device__ float g_P[2 * 32 * 32];  // [h][i][j]

__global__ void precompute_kernel(const float* __restrict__ w_attn,
                                  const float* __restrict__ w_proj) {
    int t = blockIdx.x * blockDim.x + threadIdx.x;
    if (t >= 4096) return;
    int which = t >> 11;   // 0 = M, 1 = P
    int r = t & 2047;
    int h = r >> 10;
    int i = (r >> 5) & 31;
    int j = r & 31;
    float acc = 0.f;
    if (which == 0) {
        #pragma unroll
        for (int d = 0; d < 16; d++)
            acc += w_attn[i * 96 + h * 16 + d] * w_attn[j * 96 + 32 + h * 16 + d];
        g_M[r] = acc * 0.25f;  // 1/sqrt(16)
    } else {
        #pragma unroll
        for (int d = 0; d < 16; d++)
            acc += w_attn[i * 96 + 64 + h * 16 + d] * w_proj[(h * 16 + d) * 32 + j];
        g_P[r] = acc;
    }
}

__device__ __forceinline__ unsigned smem_u32(const void* p) {
    return (unsigned)__cvta_generic_to_shared(p);
}

__global__ void __launch_bounds__(THREADS, 2)
attn_kernel(const float* __restrict__ x, const int* __restrict__ endidx,
            float* __restrict__ out) {
    // xs[parity][slot A/B][pair][row][col]
    __shared__ __align__(16) float xs[2][2][PAIRS_PER_BLK][CBLK][XSTRIDE];
    __shared__ float4 us4[2 * PAIRS_PER_BLK][2][8];   // [warp][slot][dim4]
    __shared__ float4 ss4[2 * PAIRS_PER_BLK][2][8];
    __shared__ float  atts[2 * PAIRS_PER_BLK][2][32];
    __shared__ float  y1s[PAIRS_PER_BLK][2][2][32];   // [pair][parity][slot][lane]

    const int w    = threadIdx.x >> 5;
    const int lane = threadIdx.x & 31;
    const int p    = w >> 1;             // pair in block
    const int h    = w & 1;              // head handled by this warp
    const int pt   = (h << 5) | lane;    // thread within pair (0..63)
    const int barId = p + 1;

    // This warp's head's folded-weight columns (lane = output dim j).
    float Mc[32], Pc[32];
    {
        const float* Mb = g_M + h * 1024 + lane;
        const float* Pb = g_P + h * 1024 + lane;
        #pragma unroll
        for (int i = 0; i < 32; i++) { Mc[i] = Mb[i * 32]; Pc[i] = Pb[i * 32]; }
    }

    int bwA = blockIdx.x * PAIRS_PER_BLK + p;       // tile A this iter
    // B tile = bwA + PAIRSTRIDE (derived; not stored separately)

    // idx state: current (0), next iter (1); next-next loaded in-loop.
    int idA0 = __ldg(endidx + bwA);
    int idB0 = (bwA + PAIRSTRIDE < NTILES) ? __ldg(endidx + bwA + PAIRSTRIDE) : 0;
    int idA1 = (bwA + STEP < NTILES) ? __ldg(endidx + bwA + STEP) : 0;
    int idB1 = (bwA + STEP + PAIRSTRIDE < NTILES) ? __ldg(endidx + bwA + STEP + PAIRSTRIDE) : 0;

    // ---- async stage helper
    #define STAGE(BUF, SLOT, BW, ID) do {                                      \
        const float* _xt = x + (size_t)(BW) * (CBLK * EMB);                    \
        const int _tf = ((ID) + 1) * EMB;                                      \
        _Pragma("unroll")                                                      \
        for (int _k = 0; _k < 3; _k++) {                                       \
            int _e = pt * 4 + _k * 256;                                        \
            if (_e < _tf) {                                                    \
                unsigned _d = smem_u32(&xs[BUF][SLOT][p][_e >> 5][_e & 31]);   \
                asm volatile("cp.async.cg.shared.global [%0], [%1], 16;"       \
                             :: "r"(_d), "l"(_xt + _e) : "memory");            \
            }                                                                  \
        }                                                                      \
    } while (0)

    // ---- Prologue: stage current A,B.
    STAGE(0, 0, bwA, idA0);
    if (bwA + PAIRSTRIDE < NTILES) STAGE(0, 1, bwA + PAIRSTRIDE, idB0);
    asm volatile("cp.async.commit_group;" ::: "memory");

    int buf = 0;
    int   prevA = -1, prevB = -1;
    float pqA = 0.f, pyA = 0.f, pqB = 0.f, pyB = 0.f;

    while (bwA < NTILES) {
        const int bwB = bwA + PAIRSTRIDE;

        asm volatile("cp.async.wait_group 0;" ::: "memory");
        asm volatile("bar.sync %0, 64;" :: "r"(barId) : "memory");

        // ---- Store previous iteration's outputs (warp0).
        if (h == 0) {
            if (prevA >= 0) out[prevA * EMB + lane] = pqA + pyA + y1s[p][buf ^ 1][0][lane];
            if (prevB >= 0) out[prevB * EMB + lane] = pqB + pyB + y1s[p][buf ^ 1][1][lane];
        }

        // ---- idx for iter+2; prefetch next iter's tiles into buf^1.
        const int nbwA = bwA + STEP;
        const int idA2 = (nbwA + STEP < NTILES) ? __ldg(endidx + nbwA + STEP) : 0;
        const int idB2 = (nbwA + STEP + PAIRSTRIDE < NTILES)
                             ? __ldg(endidx + nbwA + STEP + PAIRSTRIDE) : 0;
        if (nbwA < NTILES)              STAGE(buf ^ 1, 0, nbwA, idA1);
        if (nbwA + PAIRSTRIDE < NTILES) STAGE(buf ^ 1, 1, nbwA + PAIRSTRIDE, idB1);
        asm volatile("cp.async.commit_group;" ::: "memory");

        const int nkA = idA0 + 1;
        const int nkB = idB0 + 1;

        // ---- q rows (direct broadcast reads) + residual values.
        const float qvA = xs[buf][0][p][idA0][lane];
        const float qvB = xs[buf][1][p][idB0][lane];
        const float4* qrA = reinterpret_cast<const float4*>(&xs[buf][0][p][idA0][0]);
        const float4* qrB = reinterpret_cast<const float4*>(&xs[buf][1][p][idB0][0]);

        // ---- u = q @ M_h for A and B, interleaved.
        float uA = 0.f, uB = 0.f;
        #pragma unroll
        for (int i4 = 0; i4 < 8; i4++) {
            const float4 qa = qrA[i4];
            const float4 qb = qrB[i4];
            const int i = i4 * 4;
            uA = fmaf(qa.x, Mc[i + 0], uA);  uB = fmaf(qb.x, Mc[i + 0], uB);
            uA = fmaf(qa.y, Mc[i + 1], uA);  uB = fmaf(qb.y, Mc[i + 1], uB);
            uA = fmaf(qa.z, Mc[i + 2], uA);  uB = fmaf(qb.z, Mc[i + 2], uB);
            uA = fmaf(qa.w, Mc[i + 3], uA);  uB = fmaf(qb.w, Mc[i + 3], uB);
        }
        reinterpret_cast<float*>(us4[w][0])[lane] = uA;
        reinterpret_cast<float*>(us4[w][1])[lane] = uB;
        __syncwarp();

        // ---- scores, branch-free (clamped row; zeroed via select).
        const int rA = (lane < nkA) ? lane : idA0;
        const int rB = (lane < nkB) ? lane : idB0;
        const float4* xrA = reinterpret_cast<const float4*>(&xs[buf][0][p][rA][0]);
        const float4* xrB = reinterpret_cast<const float4*>(&xs[buf][1][p][rB][0]);
        float aA = 0.f, aB = 0.f;
        #pragma unroll
        for (int i4 = 0; i4 < 8; i4++) {
            const float4 ua = us4[w][0][i4];
            const float4 xa = xrA[i4];
            const float4 ub = us4[w][1][i4];
            const float4 xb = xrB[i4];
            aA = fmaf(ua.x, xa.x, aA);  aB = fmaf(ub.x, xb.x, aB);
            aA = fmaf(ua.y, xa.y, aA);  aB = fmaf(ub.y, xb.y, aB);
            aA = fmaf(ua.z, xa.z, aA);  aB = fmaf(ub.z, xb.z, aB);
            aA = fmaf(ua.w, xa.w, aA);  aB = fmaf(ub.w, xb.w, aB);
        }
        // No max-shift: std(sc)=4, overflow needs sc>88 (22 sigma) — safe.
        const float eA = (lane < nkA) ? __expf(aA) : 0.f;
        const float eB = (lane < nkB) ? __expf(aB) : 0.f;
        atts[w][0][lane] = eA;
        atts[w][1][lane] = eB;
        __syncwarp();

        // ---- softmax sums (interleaved chains); consumed at the divides.
        float sumA = eA, sumB = eB;
        #pragma unroll
        for (int o = 16; o > 0; o >>= 1) {
            sumA += __shfl_xor_sync(0xffffffffu, sumA, o);
            sumB += __shfl_xor_sync(0xffffffffu, sumB, o);
        }

        // ---- s = sum_r att_r * x_r  (lane = dim i), A then B (B overlaps A tail).
        float sA = 0.f;
        for (int r = 0; r < nkA; r++)
            sA = fmaf(atts[w][0][r], xs[buf][0][p][r][lane], sA);
        float sB = 0.f;
        for (int r = 0; r < nkB; r++)
            sB = fmaf(atts[w][1][r], xs[buf][1][p][r][lane], sB);
        sA = __fdividef(sA, sumA);
        sB = __fdividef(sB, sumB);
        reinterpret_cast<float*>(ss4[w][0])[lane] = sA;
        reinterpret_cast<float*>(ss4[w][1])[lane] = sB;
        __syncwarp();

        // ---- y = s @ P_h for A and B, interleaved.
        float yA = 0.f, yB = 0.f;
        #pragma unroll
        for (int i4 = 0; i4 < 8; i4++) {
            const float4 sa = ss4[w][0][i4];
            const float4 sb = ss4[w][1][i4];
            const int i = i4 * 4;
            yA = fmaf(sa.x, Pc[i + 0], yA);  yB = fmaf(sb.x, Pc[i + 0], yB);
            yA = fmaf(sa.y, Pc[i + 1], yA);  yB = fmaf(sb.y, Pc[i + 1], yB);
            yA = fmaf(sa.z, Pc[i + 2], yA);  yB = fmaf(sb.z, Pc[i + 2], yB);
            yA = fmaf(sa.w, Pc[i + 3], yA);  yB = fmaf(sb.w, Pc[i + 3], yB);
        }

        // ---- defer combine: warp1 publishes, warp0 stores after next bar.
        if (h == 1) {
            y1s[p][buf][0][lane] = yA;
            y1s[p][buf][1][lane] = yB;
        } else {
            pqA = qvA; pyA = yA; prevA = bwA;
            pqB = qvB; pyB = yB; prevB = (bwB < NTILES) ? bwB : -1;
        }

        bwA = nbwA;
        idA0 = idA1; idB0 = idB1;
        idA1 = idA2; idB1 = idB2;
        buf ^= 1;
    }

    // ---- Epilogue: flush last outputs.
    asm volatile("bar.sync %0, 64;" :: "r"(barId) : "memory");
    if (h == 0) {
        if (prevA >= 0) out[prevA * EMB + lane] = pqA + pyA + y1s[p][buf ^ 1][0][lane];
        if (prevB >= 0) out[prevB * EMB + lane] = pqB + pyB + y1s[p][buf ^ 1][1][lane];
    }
    #undef STAGE
}

extern "C" void kernel_launch(void* const* d_in, const int* in_sizes, int n_in,
                              void* d_out, int out_size) {
    const float* x      = (const float*)d_in[0];
    const int*   endidx = (const int*)d_in[1];
    const float* w_attn = (const float*)d_in[2];
    const float* w_proj = (const float*)d_in[3];
    float* out = (float*)d_out;

    precompute_kernel<<<16, 256>>>(w_attn, w_proj);
    attn_kernel<<<GRID, THREADS>>>(x, endidx, out);
}